// round 2
// baseline (speedup 1.0000x reference)
#include <cuda_runtime.h>
#include <math.h>

#define NMAX 100000
#define EMAX 1600000
#define HID 128
#define NGRAPH 64

// ---------------- device scratch (allocation-free rule: static globals) ----------------
__device__ float g_y[(size_t)NMAX * HID];      // dinv[n] * (x @ W_gcn)[n]
__device__ float g_S[(size_t)NMAX * HID];      // seeded with y (self loop), edges red-add into it
__device__ float g_dinv[NMAX];
__device__ int   g_deg[NMAX];
__device__ float g_gsum[NGRAPH * HID];
__device__ float g_gcnt[NGRAPH];
__device__ float g_gatesX[NGRAPH * 4 * HID];   // pooled @ w_ih^T + b_ih + b_hh, per step

// ---------------- init: zero accumulators ----------------
__global__ void k_init(int N) {
    int i = blockIdx.x * blockDim.x + threadIdx.x;
    if (i < N) g_deg[i] = 0;
    if (i < NGRAPH * HID) g_gsum[i] = 0.f;
    if (i < NGRAPH) g_gcnt[i] = 0.f;
}

// ---------------- degree histogram over col ----------------
__global__ void k_deg(const int* __restrict__ ei, int E) {
    int e = blockIdx.x * blockDim.x + threadIdx.x;
    if (e < E) {
        int col = __ldg(&ei[(size_t)E + e]);
        atomicAdd(&g_deg[col], 1);
    }
}

__global__ void k_dinv(int N) {
    int i = blockIdx.x * blockDim.x + threadIdx.x;
    if (i < N) g_dinv[i] = rsqrtf((float)g_deg[i] + 1.0f);
}

// ---------------- GEMM: y[n] = dinv[n] * (x[n] @ W); S[n] = y[n] ----------------
// Tile 128(M) x 128(N), K=128 in chunks of 32. 256 threads, 8x8 micro-tile.
__global__ __launch_bounds__(256) void k_gemm(const float* __restrict__ x,
                                              const float* __restrict__ W, int M) {
    __shared__ float xsT[32][132];   // [k][row], padded vs bank conflicts
    __shared__ float ws[32][128];    // [k][col]
    int tid = threadIdx.x;
    int ty = tid >> 4, tx = tid & 15;
    int row0 = blockIdx.x * 128;

    float acc[8][8];
#pragma unroll
    for (int i = 0; i < 8; i++)
#pragma unroll
        for (int j = 0; j < 8; j++) acc[i][j] = 0.f;

    for (int kc = 0; kc < 128; kc += 32) {
        // load x tile (128 rows x 32 k) transposed into smem
#pragma unroll
        for (int it = 0; it < 4; it++) {
            int f4 = tid + it * 256;
            int r = f4 >> 3, kq = f4 & 7;
            int grow = row0 + r;
            float4 v = make_float4(0.f, 0.f, 0.f, 0.f);
            if (grow < M)
                v = __ldg((const float4*)(x + (size_t)grow * 128 + kc + kq * 4));
            xsT[kq * 4 + 0][r] = v.x;
            xsT[kq * 4 + 1][r] = v.y;
            xsT[kq * 4 + 2][r] = v.z;
            xsT[kq * 4 + 3][r] = v.w;
        }
        // load W tile (32 k x 128 cols)
#pragma unroll
        for (int it = 0; it < 4; it++) {
            int f4 = tid + it * 256;
            int wr = f4 >> 5, wc = (f4 & 31) * 4;
            float4 v = __ldg((const float4*)(W + (size_t)(kc + wr) * 128 + wc));
            *(float4*)&ws[wr][wc] = v;
        }
        __syncthreads();
#pragma unroll
        for (int k = 0; k < 32; k++) {
            float rx[8];
#pragma unroll
            for (int i = 0; i < 8; i++) rx[i] = xsT[k][ty * 8 + i];
            float4 wa = *(const float4*)&ws[k][tx * 8];
            float4 wb = *(const float4*)&ws[k][tx * 8 + 4];
            float rw[8] = {wa.x, wa.y, wa.z, wa.w, wb.x, wb.y, wb.z, wb.w};
#pragma unroll
            for (int i = 0; i < 8; i++)
#pragma unroll
                for (int j = 0; j < 8; j++) acc[i][j] = fmaf(rx[i], rw[j], acc[i][j]);
        }
        __syncthreads();
    }

#pragma unroll
    for (int i = 0; i < 8; i++) {
        int n = row0 + ty * 8 + i;
        if (n < M) {
            float dv = g_dinv[n];
            float4 a = make_float4(acc[i][0] * dv, acc[i][1] * dv, acc[i][2] * dv, acc[i][3] * dv);
            float4 b = make_float4(acc[i][4] * dv, acc[i][5] * dv, acc[i][6] * dv, acc[i][7] * dv);
            size_t off = (size_t)n * 128 + tx * 8;
            *(float4*)&g_y[off] = a;
            *(float4*)&g_y[off + 4] = b;
            *(float4*)&g_S[off] = a;
            *(float4*)&g_S[off + 4] = b;
        }
    }
}

// ---------------- edge scatter: one warp per edge, S[col] += y[row] ----------------
__global__ __launch_bounds__(256) void k_scatter(const int* __restrict__ ei, int E) {
    int warp = (int)((blockIdx.x * (unsigned)blockDim.x + threadIdx.x) >> 5);
    int lane = threadIdx.x & 31;
    if (warp >= E) return;
    int row = __ldg(&ei[warp]);
    int col = __ldg(&ei[(size_t)E + warp]);
    float4 v = __ldg((const float4*)(g_y + (size_t)row * 128 + lane * 4));
    float* dst = g_S + (size_t)col * 128 + lane * 4;
    asm volatile("red.global.add.v4.f32 [%0], {%1,%2,%3,%4};"
                 :: "l"(dst), "f"(v.x), "f"(v.y), "f"(v.z), "f"(v.w) : "memory");
}

// ---------------- finalize relu(dinv*S + b) + mean-pool accumulation ----------------
// batch is sorted; each block handles 512 contiguous nodes, one thread per dim,
// running sum flushed on graph change -> very few float atomics.
__global__ __launch_bounds__(128) void k_pool(const int* __restrict__ batch,
                                              const float* __restrict__ b_gcn, int N) {
    int d = threadIdx.x;
    int s = blockIdx.x * 512;
    if (s >= N) return;
    int e = min(s + 512, N);
    float bb = __ldg(&b_gcn[d]);
    int curg = __ldg(&batch[s]);
    float run = 0.f, crun = 0.f;
    for (int n = s; n < e; n++) {
        int gg = __ldg(&batch[n]);
        if (gg != curg) {
            atomicAdd(&g_gsum[curg * HID + d], run);
            if (d == 0) atomicAdd(&g_gcnt[curg], crun);
            run = 0.f; crun = 0.f; curg = gg;
        }
        float v = g_dinv[n] * g_S[(size_t)n * HID + d] + bb;
        run += fmaxf(v, 0.f);
        crun += 1.f;
    }
    atomicAdd(&g_gsum[curg * HID + d], run);
    if (d == 0) atomicAdd(&g_gcnt[curg], crun);
}

// ---------------- input-side LSTM gates: gatesX[t] = pooled[t] @ w_ih^T + b_ih + b_hh ----------------
__global__ __launch_bounds__(512) void k_gatesx(const float* __restrict__ w_ih,
                                                const float* __restrict__ b_ih,
                                                const float* __restrict__ b_hh) {
    __shared__ float p[HID];
    int t = blockIdx.x;
    if (threadIdx.x < HID) {
        float c = fmaxf(g_gcnt[t], 1.f);
        p[threadIdx.x] = g_gsum[t * HID + threadIdx.x] / c;
    }
    __syncthreads();
    int gg = threadIdx.x;
    const float4* wr = (const float4*)(w_ih + (size_t)gg * HID);
    float acc = __ldg(&b_ih[gg]) + __ldg(&b_hh[gg]);
#pragma unroll
    for (int j = 0; j < 32; j++) {
        float4 w = __ldg(wr + j);
        acc += w.x * p[j * 4] + w.y * p[j * 4 + 1] + w.z * p[j * 4 + 2] + w.w * p[j * 4 + 3];
    }
    g_gatesX[t * 512 + gg] = acc;
}

// ---------------- recurrent LSTM (single persistent block) + final FC ----------------
__global__ __launch_bounds__(512) void k_lstm(const float* __restrict__ w_hh,
                                              const float* __restrict__ W_fc,
                                              const float* __restrict__ b_fc,
                                              float* __restrict__ out) {
    __shared__ float sh[HID];            // current h
    __shared__ float sg[4 * HID];        // gate pre-activations
    __shared__ float shs[NGRAPH * HID];  // all hidden states for FC
    int tid = threadIdx.x;
    float c = 0.f;
    if (tid < HID) sh[tid] = 0.f;
    __syncthreads();
    const float4* wr = (const float4*)(w_hh + (size_t)tid * HID);
    for (int t = 0; t < NGRAPH; t++) {
        float acc = g_gatesX[t * 512 + tid];
#pragma unroll
        for (int j = 0; j < 32; j++) {
            float4 w = __ldg(wr + j);
            float4 h4 = *(const float4*)&sh[j * 4];
            acc += w.x * h4.x + w.y * h4.y + w.z * h4.z + w.w * h4.w;
        }
        sg[tid] = acc;
        __syncthreads();
        if (tid < HID) {
            float iv = 1.f / (1.f + expf(-sg[tid]));
            float fv = 1.f / (1.f + expf(-sg[HID + tid]));
            float gv = tanhf(sg[2 * HID + tid]);
            float ov = 1.f / (1.f + expf(-sg[3 * HID + tid]));
            c = fv * c + iv * gv;
            float h = ov * tanhf(c);
            sh[tid] = h;
            shs[t * HID + tid] = h;
        }
        __syncthreads();
    }
    // FC: out[t][k] = hs[t] . W_fc[k] + b_fc[k]
    for (int idx = tid; idx < NGRAPH * 10; idx += 512) {
        int t = idx / 10, k = idx % 10;
        float acc = __ldg(&b_fc[k]);
        const float* wf = W_fc + (size_t)k * HID;
        for (int j = 0; j < HID; j++) acc += shs[t * HID + j] * __ldg(&wf[j]);
        out[idx] = acc;
    }
}

// ---------------- launch ----------------
extern "C" void kernel_launch(void* const* d_in, const int* in_sizes, int n_in,
                              void* d_out, int out_size) {
    const float* x      = (const float*)d_in[0];
    const int*   ei     = (const int*)d_in[1];
    const int*   batch  = (const int*)d_in[2];
    const float* W_gcn  = (const float*)d_in[3];
    const float* b_gcn  = (const float*)d_in[4];
    const float* w_ih   = (const float*)d_in[5];
    const float* w_hh   = (const float*)d_in[6];
    const float* b_ih   = (const float*)d_in[7];
    const float* b_hh   = (const float*)d_in[8];
    const float* W_fc   = (const float*)d_in[9];
    const float* b_fc   = (const float*)d_in[10];
    float* out = (float*)d_out;

    int N = in_sizes[2];       // 100000 nodes
    int E = in_sizes[1] / 2;   // 1600000 edges

    k_init<<<(N + 255) / 256, 256>>>(N);
    k_deg<<<(E + 255) / 256, 256>>>(ei, E);
    k_dinv<<<(N + 255) / 256, 256>>>(N);
    k_gemm<<<(N + 127) / 128, 256>>>(x, W_gcn, N);
    long long scatter_threads = (long long)E * 32;
    k_scatter<<<(unsigned)((scatter_threads + 255) / 256), 256>>>(ei, E);
    k_pool<<<(N + 511) / 512, 128>>>(batch, b_gcn, N);
    k_gatesx<<<NGRAPH, 512>>>(w_ih, b_ih, b_hh);
    k_lstm<<<1, 512>>>(w_hh, W_fc, b_fc, out);
}

// round 3
// speedup vs baseline: 1.2344x; 1.2344x over previous
#include <cuda_runtime.h>
#include <math.h>

#define NMAX 100000
#define EMAX 1600000
#define HID 128
#define NGRAPH 64
#define SCAN_BLK 512

// ---------------- device scratch ----------------
__device__ float g_y[(size_t)NMAX * HID];      // dinv[n] * (x @ W_gcn)[n]
__device__ float g_dinv[NMAX];
__device__ int   g_deg[NMAX];
__device__ int   g_start[NMAX + 1];            // CSR offsets (by col)
__device__ int   g_cursor[NMAX];               // fill cursors
__device__ int   g_csr_src[EMAX];              // source (row) ids grouped by col
__device__ int   g_part[(NMAX + SCAN_BLK - 1) / SCAN_BLK];
__device__ int   g_partscan[(NMAX + SCAN_BLK - 1) / SCAN_BLK];
__device__ float g_gsum[NGRAPH * HID];
__device__ float g_gcnt[NGRAPH];
__device__ float g_gatesX[NGRAPH * 4 * HID];

// ---------------- init ----------------
__global__ void k_init(int N) {
    int i = blockIdx.x * blockDim.x + threadIdx.x;
    if (i < N) g_deg[i] = 0;
    if (i < NGRAPH * HID) g_gsum[i] = 0.f;
    if (i < NGRAPH) g_gcnt[i] = 0.f;
}

// ---------------- degree histogram over col ----------------
__global__ void k_deg(const int* __restrict__ ei, int E) {
    int e = blockIdx.x * blockDim.x + threadIdx.x;
    if (e < E) atomicAdd(&g_deg[__ldg(&ei[(size_t)E + e])], 1);
}

// ---------------- scan pass 1: block sums + dinv ----------------
__global__ __launch_bounds__(SCAN_BLK) void k_scan1(int N) {
    int i = blockIdx.x * SCAN_BLK + threadIdx.x;
    int v = (i < N) ? g_deg[i] : 0;
    if (i < N) g_dinv[i] = rsqrtf((float)v + 1.0f);
    // warp reduce
    int s = v;
    for (int o = 16; o > 0; o >>= 1) s += __shfl_down_sync(0xffffffffu, s, o);
    __shared__ int ws[16];
    int wid = threadIdx.x >> 5, lane = threadIdx.x & 31;
    if (lane == 0) ws[wid] = s;
    __syncthreads();
    if (threadIdx.x < 16) {
        int t = ws[threadIdx.x];
        for (int o = 8; o > 0; o >>= 1) t += __shfl_down_sync(0xffffu, t, o);
        if (threadIdx.x == 0) g_part[blockIdx.x] = t;
    }
}

// ---------------- scan pass 2: exclusive scan of block partials ----------------
__global__ void k_scan2(int NB) {
    if (threadIdx.x == 0) {
        int run = 0;
        for (int b = 0; b < NB; b++) { g_partscan[b] = run; run += g_part[b]; }
    }
}

// ---------------- scan pass 3: block exclusive scan -> g_start, g_cursor ----------------
__global__ __launch_bounds__(SCAN_BLK) void k_scan3(int N) {
    int i = blockIdx.x * SCAN_BLK + threadIdx.x;
    int v = (i < N) ? g_deg[i] : 0;
    int lane = threadIdx.x & 31, wid = threadIdx.x >> 5;
    // warp inclusive scan
    int x = v;
    for (int o = 1; o < 32; o <<= 1) {
        int t = __shfl_up_sync(0xffffffffu, x, o);
        if (lane >= o) x += t;
    }
    __shared__ int ws[16];
    if (lane == 31) ws[wid] = x;
    __syncthreads();
    if (threadIdx.x < 16) {
        int t = ws[threadIdx.x];
        for (int o = 1; o < 16; o <<= 1) {
            int u = __shfl_up_sync(0xffffu, t, o);
            if (threadIdx.x >= o) t += u;
        }
        ws[threadIdx.x] = t;   // inclusive warp-partial scan
    }
    __syncthreads();
    int base = g_partscan[blockIdx.x] + (wid > 0 ? ws[wid - 1] : 0);
    int excl = base + (x - v);
    if (i < N) { g_start[i] = excl; g_cursor[i] = excl; }
    if (i == N - 1) g_start[N] = excl + v;
}

// ---------------- CSR fill ----------------
__global__ void k_fill(const int* __restrict__ ei, int E) {
    int e = blockIdx.x * blockDim.x + threadIdx.x;
    if (e < E) {
        int row = __ldg(&ei[e]);
        int col = __ldg(&ei[(size_t)E + e]);
        int slot = atomicAdd(&g_cursor[col], 1);
        g_csr_src[slot] = row;
    }
}

// ---------------- GEMM: y[n] = dinv[n] * (x[n] @ W) ----------------
__global__ __launch_bounds__(256) void k_gemm(const float* __restrict__ x,
                                              const float* __restrict__ W, int M) {
    __shared__ float xsT[32][132];
    __shared__ float ws[32][128];
    int tid = threadIdx.x;
    int ty = tid >> 4, tx = tid & 15;
    int row0 = blockIdx.x * 128;

    float acc[8][8];
#pragma unroll
    for (int i = 0; i < 8; i++)
#pragma unroll
        for (int j = 0; j < 8; j++) acc[i][j] = 0.f;

    for (int kc = 0; kc < 128; kc += 32) {
#pragma unroll
        for (int it = 0; it < 4; it++) {
            int f4 = tid + it * 256;
            int r = f4 >> 3, kq = f4 & 7;
            int grow = row0 + r;
            float4 v = make_float4(0.f, 0.f, 0.f, 0.f);
            if (grow < M)
                v = __ldg((const float4*)(x + (size_t)grow * 128 + kc + kq * 4));
            xsT[kq * 4 + 0][r] = v.x;
            xsT[kq * 4 + 1][r] = v.y;
            xsT[kq * 4 + 2][r] = v.z;
            xsT[kq * 4 + 3][r] = v.w;
        }
#pragma unroll
        for (int it = 0; it < 4; it++) {
            int f4 = tid + it * 256;
            int wr = f4 >> 5, wc = (f4 & 31) * 4;
            float4 v = __ldg((const float4*)(W + (size_t)(kc + wr) * 128 + wc));
            *(float4*)&ws[wr][wc] = v;
        }
        __syncthreads();
#pragma unroll
        for (int k = 0; k < 32; k++) {
            float rx[8];
#pragma unroll
            for (int i = 0; i < 8; i++) rx[i] = xsT[k][ty * 8 + i];
            float4 wa = *(const float4*)&ws[k][tx * 8];
            float4 wb = *(const float4*)&ws[k][tx * 8 + 4];
            float rw[8] = {wa.x, wa.y, wa.z, wa.w, wb.x, wb.y, wb.z, wb.w};
#pragma unroll
            for (int i = 0; i < 8; i++)
#pragma unroll
                for (int j = 0; j < 8; j++) acc[i][j] = fmaf(rx[i], rw[j], acc[i][j]);
        }
        __syncthreads();
    }

#pragma unroll
    for (int i = 0; i < 8; i++) {
        int n = row0 + ty * 8 + i;
        if (n < M) {
            float dv = g_dinv[n];
            float4 a = make_float4(acc[i][0] * dv, acc[i][1] * dv, acc[i][2] * dv, acc[i][3] * dv);
            float4 b = make_float4(acc[i][4] * dv, acc[i][5] * dv, acc[i][6] * dv, acc[i][7] * dv);
            size_t off = (size_t)n * 128 + tx * 8;
            *(float4*)&g_y[off] = a;
            *(float4*)&g_y[off + 4] = b;
        }
    }
}

// ---------------- fused gather-aggregate + relu + mean-pool ----------------
// One warp per node; lane holds dims [lane*4, lane*4+4). Block covers 512
// contiguous nodes (8 warps, stride 8). Pool sums kept in registers, flushed
// on graph change (batch sorted) via red.global.
__device__ __forceinline__ void pool_flush(int g, float4 run, float crun, int lane) {
    float* dst = g_gsum + g * HID + lane * 4;
    asm volatile("red.global.add.v4.f32 [%0], {%1,%2,%3,%4};"
                 :: "l"(dst), "f"(run.x), "f"(run.y), "f"(run.z), "f"(run.w) : "memory");
    if (lane == 0) atomicAdd(&g_gcnt[g], crun);
}

__global__ __launch_bounds__(256) void k_agg(const int* __restrict__ batch,
                                             const float* __restrict__ b_gcn, int N) {
    int lane = threadIdx.x & 31, wid = threadIdx.x >> 5;
    int s0 = blockIdx.x * 512;
    int e0 = min(s0 + 512, N);
    int n0 = s0 + wid;
    if (n0 >= e0) return;

    float4 bb = __ldg((const float4*)(b_gcn + lane * 4));
    int curg = __ldg(&batch[n0]);
    float4 run = make_float4(0.f, 0.f, 0.f, 0.f);
    float crun = 0.f;

    for (int n = n0; n < e0; n += 8) {
        int gg = __ldg(&batch[n]);
        if (gg != curg) {
            pool_flush(curg, run, crun, lane);
            run = make_float4(0.f, 0.f, 0.f, 0.f);
            crun = 0.f;
            curg = gg;
        }
        int st = __ldg(&g_start[n]);
        int en = __ldg(&g_start[n + 1]);
        // self-loop term
        float4 acc = *(const float4*)(g_y + (size_t)n * HID + lane * 4);
        for (int base = st; base < en; base += 32) {
            int cnt = min(32, en - base);
            int id = (lane < cnt) ? __ldg(&g_csr_src[base + lane]) : 0;
            int j = 0;
            for (; j + 4 <= cnt; j += 4) {
                int a0 = __shfl_sync(0xffffffffu, id, j);
                int a1 = __shfl_sync(0xffffffffu, id, j + 1);
                int a2 = __shfl_sync(0xffffffffu, id, j + 2);
                int a3 = __shfl_sync(0xffffffffu, id, j + 3);
                float4 v0 = __ldg((const float4*)(g_y + (size_t)a0 * HID + lane * 4));
                float4 v1 = __ldg((const float4*)(g_y + (size_t)a1 * HID + lane * 4));
                float4 v2 = __ldg((const float4*)(g_y + (size_t)a2 * HID + lane * 4));
                float4 v3 = __ldg((const float4*)(g_y + (size_t)a3 * HID + lane * 4));
                acc.x += v0.x + v1.x + v2.x + v3.x;
                acc.y += v0.y + v1.y + v2.y + v3.y;
                acc.z += v0.z + v1.z + v2.z + v3.z;
                acc.w += v0.w + v1.w + v2.w + v3.w;
            }
            for (; j < cnt; j++) {
                int a0 = __shfl_sync(0xffffffffu, id, j);
                float4 v0 = __ldg((const float4*)(g_y + (size_t)a0 * HID + lane * 4));
                acc.x += v0.x; acc.y += v0.y; acc.z += v0.z; acc.w += v0.w;
            }
        }
        float dv = __ldg(&g_dinv[n]);
        run.x += fmaxf(fmaf(acc.x, dv, bb.x), 0.f);
        run.y += fmaxf(fmaf(acc.y, dv, bb.y), 0.f);
        run.z += fmaxf(fmaf(acc.z, dv, bb.z), 0.f);
        run.w += fmaxf(fmaf(acc.w, dv, bb.w), 0.f);
        crun += 1.f;
    }
    pool_flush(curg, run, crun, lane);
}

// ---------------- input-side LSTM gates ----------------
__global__ __launch_bounds__(512) void k_gatesx(const float* __restrict__ w_ih,
                                                const float* __restrict__ b_ih,
                                                const float* __restrict__ b_hh) {
    __shared__ float p[HID];
    int t = blockIdx.x;
    if (threadIdx.x < HID) {
        float c = fmaxf(g_gcnt[t], 1.f);
        p[threadIdx.x] = g_gsum[t * HID + threadIdx.x] / c;
    }
    __syncthreads();
    int gg = threadIdx.x;
    const float4* wr = (const float4*)(w_ih + (size_t)gg * HID);
    float acc = __ldg(&b_ih[gg]) + __ldg(&b_hh[gg]);
#pragma unroll
    for (int j = 0; j < 32; j++) {
        float4 w = __ldg(wr + j);
        acc += w.x * p[j * 4] + w.y * p[j * 4 + 1] + w.z * p[j * 4 + 2] + w.w * p[j * 4 + 3];
    }
    g_gatesX[t * 512 + gg] = acc;
}

// ---------------- recurrent LSTM + final FC ----------------
__global__ __launch_bounds__(512) void k_lstm(const float* __restrict__ w_hh,
                                              const float* __restrict__ W_fc,
                                              const float* __restrict__ b_fc,
                                              float* __restrict__ out) {
    __shared__ float sh[HID];
    __shared__ float sg[4 * HID];
    __shared__ float shs[NGRAPH * HID];
    int tid = threadIdx.x;
    float c = 0.f;
    if (tid < HID) sh[tid] = 0.f;
    __syncthreads();
    const float4* wr = (const float4*)(w_hh + (size_t)tid * HID);
    for (int t = 0; t < NGRAPH; t++) {
        float acc = g_gatesX[t * 512 + tid];
#pragma unroll
        for (int j = 0; j < 32; j++) {
            float4 w = __ldg(wr + j);
            float4 h4 = *(const float4*)&sh[j * 4];
            acc += w.x * h4.x + w.y * h4.y + w.z * h4.z + w.w * h4.w;
        }
        sg[tid] = acc;
        __syncthreads();
        if (tid < HID) {
            float iv = 1.f / (1.f + expf(-sg[tid]));
            float fv = 1.f / (1.f + expf(-sg[HID + tid]));
            float gv = tanhf(sg[2 * HID + tid]);
            float ov = 1.f / (1.f + expf(-sg[3 * HID + tid]));
            c = fv * c + iv * gv;
            float h = ov * tanhf(c);
            sh[tid] = h;
            shs[t * HID + tid] = h;
        }
        __syncthreads();
    }
    for (int idx = tid; idx < NGRAPH * 10; idx += 512) {
        int t = idx / 10, k = idx % 10;
        float acc = __ldg(&b_fc[k]);
        const float* wf = W_fc + (size_t)k * HID;
        for (int j = 0; j < HID; j++) acc += shs[t * HID + j] * __ldg(&wf[j]);
        out[idx] = acc;
    }
}

// ---------------- launch ----------------
extern "C" void kernel_launch(void* const* d_in, const int* in_sizes, int n_in,
                              void* d_out, int out_size) {
    const float* x      = (const float*)d_in[0];
    const int*   ei     = (const int*)d_in[1];
    const int*   batch  = (const int*)d_in[2];
    const float* W_gcn  = (const float*)d_in[3];
    const float* b_gcn  = (const float*)d_in[4];
    const float* w_ih   = (const float*)d_in[5];
    const float* w_hh   = (const float*)d_in[6];
    const float* b_ih   = (const float*)d_in[7];
    const float* b_hh   = (const float*)d_in[8];
    const float* W_fc   = (const float*)d_in[9];
    const float* b_fc   = (const float*)d_in[10];
    float* out = (float*)d_out;

    int N = in_sizes[2];       // 100000 nodes
    int E = in_sizes[1] / 2;   // 1600000 edges
    int NB = (N + SCAN_BLK - 1) / SCAN_BLK;

    k_init<<<(N + 255) / 256, 256>>>(N);
    k_deg<<<(E + 255) / 256, 256>>>(ei, E);
    k_scan1<<<NB, SCAN_BLK>>>(N);
    k_scan2<<<1, 32>>>(NB);
    k_scan3<<<NB, SCAN_BLK>>>(N);
    k_fill<<<(E + 255) / 256, 256>>>(ei, E);
    k_gemm<<<(N + 127) / 128, 256>>>(x, W_gcn, N);
    k_agg<<<(N + 511) / 512, 256>>>(batch, b_gcn, N);
    k_gatesx<<<NGRAPH, 512>>>(w_ih, b_ih, b_hh);
    k_lstm<<<1, 512>>>(w_hh, W_fc, b_fc, out);
}

// round 4
// speedup vs baseline: 1.8012x; 1.4592x over previous
#include <cuda_runtime.h>
#include <cuda_fp16.h>
#include <math.h>

#define NMAX 100000
#define EMAX 1600000
#define HID 128
#define NGRAPH 64
#define SCAN_BLK 512

// ---------------- device scratch ----------------
__device__ float g_y[(size_t)NMAX * HID];
__device__ float g_dinv[NMAX];
__device__ int   g_deg[NMAX];
__device__ int   g_start[NMAX + 1];
__device__ int   g_cursor[NMAX];
__device__ int   g_csr_src[EMAX];
__device__ int   g_part[(NMAX + SCAN_BLK - 1) / SCAN_BLK];
__device__ int   g_partscan[(NMAX + SCAN_BLK - 1) / SCAN_BLK];
__device__ float g_gsum[NGRAPH * HID];
__device__ float g_gcnt[NGRAPH];
__device__ float g_gatesX[NGRAPH * 4 * HID];
__device__ __half g_whh_h[4 * HID * HID];      // fp16 copy of w_hh (64 KB, L1-resident)

// ---------------- init ----------------
__global__ void k_init(int N) {
    int i = blockIdx.x * blockDim.x + threadIdx.x;
    if (i < N) g_deg[i] = 0;
    if (i < NGRAPH * HID) g_gsum[i] = 0.f;
    if (i < NGRAPH) g_gcnt[i] = 0.f;
}

// ---------------- degree histogram over col ----------------
__global__ void k_deg(const int* __restrict__ ei, int E) {
    int e = blockIdx.x * blockDim.x + threadIdx.x;
    if (e < E) atomicAdd(&g_deg[__ldg(&ei[(size_t)E + e])], 1);
}

// ---------------- scan pass 1: block sums + dinv ----------------
__global__ __launch_bounds__(SCAN_BLK) void k_scan1(int N) {
    int i = blockIdx.x * SCAN_BLK + threadIdx.x;
    int v = (i < N) ? g_deg[i] : 0;
    if (i < N) g_dinv[i] = rsqrtf((float)v + 1.0f);
    int s = v;
    for (int o = 16; o > 0; o >>= 1) s += __shfl_down_sync(0xffffffffu, s, o);
    __shared__ int ws[16];
    int wid = threadIdx.x >> 5, lane = threadIdx.x & 31;
    if (lane == 0) ws[wid] = s;
    __syncthreads();
    if (threadIdx.x < 16) {
        int t = ws[threadIdx.x];
        for (int o = 8; o > 0; o >>= 1) t += __shfl_down_sync(0xffffu, t, o);
        if (threadIdx.x == 0) g_part[blockIdx.x] = t;
    }
}

// ---------------- scan pass 2: parallel exclusive scan of <=256 block partials ----------------
__global__ __launch_bounds__(256) void k_scan2(int NB) {
    int tid = threadIdx.x;
    int v = (tid < NB) ? g_part[tid] : 0;
    int lane = tid & 31, wid = tid >> 5;
    int x = v;
    for (int o = 1; o < 32; o <<= 1) {
        int t = __shfl_up_sync(0xffffffffu, x, o);
        if (lane >= o) x += t;
    }
    __shared__ int ws[8];
    if (lane == 31) ws[wid] = x;
    __syncthreads();
    if (tid < 8) {
        int t = ws[tid];
        for (int o = 1; o < 8; o <<= 1) {
            int u = __shfl_up_sync(0xffu, t, o);
            if (tid >= o) t += u;
        }
        ws[tid] = t;
    }
    __syncthreads();
    int incl = x + (wid > 0 ? ws[wid - 1] : 0);
    if (tid < NB) g_partscan[tid] = incl - v;
}

// ---------------- scan pass 3: block exclusive scan -> g_start, g_cursor ----------------
__global__ __launch_bounds__(SCAN_BLK) void k_scan3(int N) {
    int i = blockIdx.x * SCAN_BLK + threadIdx.x;
    int v = (i < N) ? g_deg[i] : 0;
    int lane = threadIdx.x & 31, wid = threadIdx.x >> 5;
    int x = v;
    for (int o = 1; o < 32; o <<= 1) {
        int t = __shfl_up_sync(0xffffffffu, x, o);
        if (lane >= o) x += t;
    }
    __shared__ int ws[16];
    if (lane == 31) ws[wid] = x;
    __syncthreads();
    if (threadIdx.x < 16) {
        int t = ws[threadIdx.x];
        for (int o = 1; o < 16; o <<= 1) {
            int u = __shfl_up_sync(0xffffu, t, o);
            if (threadIdx.x >= o) t += u;
        }
        ws[threadIdx.x] = t;
    }
    __syncthreads();
    int base = g_partscan[blockIdx.x] + (wid > 0 ? ws[wid - 1] : 0);
    int excl = base + (x - v);
    if (i < N) { g_start[i] = excl; g_cursor[i] = excl; }
    if (i == N - 1) g_start[N] = excl + v;
}

// ---------------- CSR fill ----------------
__global__ void k_fill(const int* __restrict__ ei, int E) {
    int e = blockIdx.x * blockDim.x + threadIdx.x;
    if (e < E) {
        int row = __ldg(&ei[e]);
        int col = __ldg(&ei[(size_t)E + e]);
        int slot = atomicAdd(&g_cursor[col], 1);
        g_csr_src[slot] = row;
    }
}

// ---------------- convert w_hh to fp16 ----------------
__global__ void k_cvt(const float* __restrict__ w_hh) {
    int i = blockIdx.x * blockDim.x + threadIdx.x;
    if (i < 4 * HID * HID) g_whh_h[i] = __float2half(__ldg(&w_hh[i]));
}

// ---------------- GEMM: y[n] = dinv[n] * (x[n] @ W) ----------------
// 512 threads, 128x128 tile, 4x8 micro -> ~60 regs -> 2 CTAs/SM.
__global__ __launch_bounds__(512) void k_gemm(const float* __restrict__ x,
                                              const float* __restrict__ W, int M) {
    __shared__ float xsT[32][132];
    __shared__ float ws[32][128];
    int tid = threadIdx.x;
    int ty = tid >> 4, tx = tid & 15;   // ty 0..31 (4 rows), tx 0..15 (8 cols)
    int row0 = blockIdx.x * 128;

    float acc[4][8];
#pragma unroll
    for (int i = 0; i < 4; i++)
#pragma unroll
        for (int j = 0; j < 8; j++) acc[i][j] = 0.f;

    for (int kc = 0; kc < 128; kc += 32) {
#pragma unroll
        for (int it = 0; it < 2; it++) {
            int f4 = tid + it * 512;
            int r = f4 >> 3, kq = f4 & 7;
            int grow = row0 + r;
            float4 v = make_float4(0.f, 0.f, 0.f, 0.f);
            if (grow < M)
                v = __ldg((const float4*)(x + (size_t)grow * 128 + kc + kq * 4));
            xsT[kq * 4 + 0][r] = v.x;
            xsT[kq * 4 + 1][r] = v.y;
            xsT[kq * 4 + 2][r] = v.z;
            xsT[kq * 4 + 3][r] = v.w;
        }
#pragma unroll
        for (int it = 0; it < 2; it++) {
            int f4 = tid + it * 512;
            int wr = f4 >> 5, wc = (f4 & 31) * 4;
            float4 v = __ldg((const float4*)(W + (size_t)(kc + wr) * 128 + wc));
            *(float4*)&ws[wr][wc] = v;
        }
        __syncthreads();
#pragma unroll
        for (int k = 0; k < 32; k++) {
            float rx[4];
#pragma unroll
            for (int i = 0; i < 4; i++) rx[i] = xsT[k][ty * 4 + i];
            float4 wa = *(const float4*)&ws[k][tx * 8];
            float4 wb = *(const float4*)&ws[k][tx * 8 + 4];
            float rw[8] = {wa.x, wa.y, wa.z, wa.w, wb.x, wb.y, wb.z, wb.w};
#pragma unroll
            for (int i = 0; i < 4; i++)
#pragma unroll
                for (int j = 0; j < 8; j++) acc[i][j] = fmaf(rx[i], rw[j], acc[i][j]);
        }
        __syncthreads();
    }

#pragma unroll
    for (int i = 0; i < 4; i++) {
        int n = row0 + ty * 4 + i;
        if (n < M) {
            float dv = g_dinv[n];
            float4 a = make_float4(acc[i][0] * dv, acc[i][1] * dv, acc[i][2] * dv, acc[i][3] * dv);
            float4 b = make_float4(acc[i][4] * dv, acc[i][5] * dv, acc[i][6] * dv, acc[i][7] * dv);
            size_t off = (size_t)n * 128 + tx * 8;
            *(float4*)&g_y[off] = a;
            *(float4*)&g_y[off + 4] = b;
        }
    }
}

// ---------------- fused gather-aggregate + relu + mean-pool ----------------
// One warp per node window of 16; block (8 warps) covers 128 contiguous nodes.
__device__ __forceinline__ void pool_flush(int g, float4 run, float crun, int lane) {
    float* dst = g_gsum + g * HID + lane * 4;
    asm volatile("red.global.add.v4.f32 [%0], {%1,%2,%3,%4};"
                 :: "l"(dst), "f"(run.x), "f"(run.y), "f"(run.z), "f"(run.w) : "memory");
    if (lane == 0) atomicAdd(&g_gcnt[g], crun);
}

__global__ __launch_bounds__(256) void k_agg(const int* __restrict__ batch,
                                             const float* __restrict__ b_gcn, int N) {
    int lane = threadIdx.x & 31, wid = threadIdx.x >> 5;
    int s0 = blockIdx.x * 128;
    int e0 = min(s0 + 128, N);
    int n0 = s0 + wid;
    if (n0 >= e0) return;

    float4 bb = __ldg((const float4*)(b_gcn + lane * 4));
    int curg = __ldg(&batch[n0]);
    float4 run = make_float4(0.f, 0.f, 0.f, 0.f);
    float crun = 0.f;

    for (int n = n0; n < e0; n += 8) {
        int gg = __ldg(&batch[n]);
        if (gg != curg) {
            pool_flush(curg, run, crun, lane);
            run = make_float4(0.f, 0.f, 0.f, 0.f);
            crun = 0.f;
            curg = gg;
        }
        int st = __ldg(&g_start[n]);
        int en = __ldg(&g_start[n + 1]);
        float4 acc = *(const float4*)(g_y + (size_t)n * HID + lane * 4);  // self loop
        for (int base = st; base < en; base += 32) {
            int cnt = min(32, en - base);
            int id = (lane < cnt) ? __ldg(&g_csr_src[base + lane]) : 0;
            int j = 0;
            for (; j + 4 <= cnt; j += 4) {
                int a0 = __shfl_sync(0xffffffffu, id, j);
                int a1 = __shfl_sync(0xffffffffu, id, j + 1);
                int a2 = __shfl_sync(0xffffffffu, id, j + 2);
                int a3 = __shfl_sync(0xffffffffu, id, j + 3);
                float4 v0 = __ldg((const float4*)(g_y + (size_t)a0 * HID + lane * 4));
                float4 v1 = __ldg((const float4*)(g_y + (size_t)a1 * HID + lane * 4));
                float4 v2 = __ldg((const float4*)(g_y + (size_t)a2 * HID + lane * 4));
                float4 v3 = __ldg((const float4*)(g_y + (size_t)a3 * HID + lane * 4));
                acc.x += v0.x + v1.x + v2.x + v3.x;
                acc.y += v0.y + v1.y + v2.y + v3.y;
                acc.z += v0.z + v1.z + v2.z + v3.z;
                acc.w += v0.w + v1.w + v2.w + v3.w;
            }
            for (; j < cnt; j++) {
                int a0 = __shfl_sync(0xffffffffu, id, j);
                float4 v0 = __ldg((const float4*)(g_y + (size_t)a0 * HID + lane * 4));
                acc.x += v0.x; acc.y += v0.y; acc.z += v0.z; acc.w += v0.w;
            }
        }
        float dv = __ldg(&g_dinv[n]);
        run.x += fmaxf(fmaf(acc.x, dv, bb.x), 0.f);
        run.y += fmaxf(fmaf(acc.y, dv, bb.y), 0.f);
        run.z += fmaxf(fmaf(acc.z, dv, bb.z), 0.f);
        run.w += fmaxf(fmaf(acc.w, dv, bb.w), 0.f);
        crun += 1.f;
    }
    pool_flush(curg, run, crun, lane);
}

// ---------------- input-side LSTM gates ----------------
__global__ __launch_bounds__(512) void k_gatesx(const float* __restrict__ w_ih,
                                                const float* __restrict__ b_ih,
                                                const float* __restrict__ b_hh) {
    __shared__ float p[HID];
    int t = blockIdx.x;
    if (threadIdx.x < HID) {
        float c = fmaxf(g_gcnt[t], 1.f);
        p[threadIdx.x] = g_gsum[t * HID + threadIdx.x] / c;
    }
    __syncthreads();
    int gg = threadIdx.x;
    const float4* wr = (const float4*)(w_ih + (size_t)gg * HID);
    float acc = __ldg(&b_ih[gg]) + __ldg(&b_hh[gg]);
#pragma unroll
    for (int j = 0; j < 32; j++) {
        float4 w = __ldg(wr + j);
        acc += w.x * p[j * 4] + w.y * p[j * 4 + 1] + w.z * p[j * 4 + 2] + w.w * p[j * 4 + 3];
    }
    g_gatesX[t * 512 + gg] = acc;
}

// ---------------- recurrent LSTM (fp16 weights, L1-resident) + fused FC ----------------
__global__ __launch_bounds__(512) void k_lstm(const float* __restrict__ W_fc,
                                              const float* __restrict__ b_fc,
                                              float* __restrict__ out) {
    __shared__ float sh[HID];
    __shared__ float sg[4 * HID];
    int tid = threadIdx.x;
    float c = 0.f;
    if (tid < HID) sh[tid] = 0.f;
    __syncthreads();
    const uint4* wr = (const uint4*)(g_whh_h + (size_t)tid * HID);  // 16 x uint4 = 128 halves
    for (int t = 0; t < NGRAPH; t++) {
        float acc = g_gatesX[t * 512 + tid];
#pragma unroll
        for (int j = 0; j < 16; j++) {
            uint4 w = __ldg(&wr[j]);
            float2 a0 = __half22float2(*(const __half2*)&w.x);
            float2 a1 = __half22float2(*(const __half2*)&w.y);
            float2 a2 = __half22float2(*(const __half2*)&w.z);
            float2 a3 = __half22float2(*(const __half2*)&w.w);
            const float* h = &sh[j * 8];
            acc = fmaf(a0.x, h[0], acc); acc = fmaf(a0.y, h[1], acc);
            acc = fmaf(a1.x, h[2], acc); acc = fmaf(a1.y, h[3], acc);
            acc = fmaf(a2.x, h[4], acc); acc = fmaf(a2.y, h[5], acc);
            acc = fmaf(a3.x, h[6], acc); acc = fmaf(a3.y, h[7], acc);
        }
        sg[tid] = acc;
        __syncthreads();
        if (tid < HID) {
            float iv = 1.f / (1.f + __expf(-sg[tid]));
            float fv = 1.f / (1.f + __expf(-sg[HID + tid]));
            float gv = tanhf(sg[2 * HID + tid]);
            float ov = 1.f / (1.f + __expf(-sg[3 * HID + tid]));
            c = fv * c + iv * gv;
            sh[tid] = ov * tanhf(c);
        }
        __syncthreads();
        // fused FC for step t: 10 warps compute out[t][k]
        if (tid < 320) {
            int k = tid >> 5, lane = tid & 31;
            const float4* wf = (const float4*)(W_fc + (size_t)k * HID);
            float4 w = __ldg(&wf[lane]);
            float4 h4 = *(const float4*)&sh[lane * 4];
            float p = w.x * h4.x + w.y * h4.y + w.z * h4.z + w.w * h4.w;
            for (int o = 16; o > 0; o >>= 1) p += __shfl_down_sync(0xffffffffu, p, o);
            if (lane == 0) out[t * 10 + k] = p + __ldg(&b_fc[k]);
        }
    }
}

// ---------------- launch ----------------
extern "C" void kernel_launch(void* const* d_in, const int* in_sizes, int n_in,
                              void* d_out, int out_size) {
    const float* x      = (const float*)d_in[0];
    const int*   ei     = (const int*)d_in[1];
    const int*   batch  = (const int*)d_in[2];
    const float* W_gcn  = (const float*)d_in[3];
    const float* b_gcn  = (const float*)d_in[4];
    const float* w_ih   = (const float*)d_in[5];
    const float* w_hh   = (const float*)d_in[6];
    const float* b_ih   = (const float*)d_in[7];
    const float* b_hh   = (const float*)d_in[8];
    const float* W_fc   = (const float*)d_in[9];
    const float* b_fc   = (const float*)d_in[10];
    float* out = (float*)d_out;

    int N = in_sizes[2];       // 100000 nodes
    int E = in_sizes[1] / 2;   // 1600000 edges
    int NB = (N + SCAN_BLK - 1) / SCAN_BLK;

    k_init<<<(N + 255) / 256, 256>>>(N);
    k_deg<<<(E + 255) / 256, 256>>>(ei, E);
    k_scan1<<<NB, SCAN_BLK>>>(N);
    k_scan2<<<1, 256>>>(NB);
    k_scan3<<<NB, SCAN_BLK>>>(N);
    k_fill<<<(E + 255) / 256, 256>>>(ei, E);
    k_cvt<<<(4 * HID * HID + 255) / 256, 256>>>(w_hh);
    k_gemm<<<(N + 127) / 128, 512>>>(x, W_gcn, N);
    k_agg<<<(N + 127) / 128, 256>>>(batch, b_gcn, N);
    k_gatesx<<<NGRAPH, 512>>>(w_ih, b_ih, b_hh);
    k_lstm<<<1, 512>>>(W_fc, b_fc, out);
}

// round 5
// speedup vs baseline: 1.9609x; 1.0886x over previous
#include <cuda_runtime.h>
#include <cuda_fp16.h>
#include <math.h>

#define NMAX 100000
#define EMAX 1600000
#define HID 128
#define NGRAPH 64
#define SCAN_BLK 512

// ---------------- device scratch ----------------
__device__ __half g_yh[(size_t)NMAX * HID];    // fp16: dinv[n] * (x @ W_gcn)[n]
__device__ float g_dinv[NMAX];
__device__ int   g_deg[NMAX];
__device__ int   g_start[NMAX + 1];
__device__ int   g_cursor[NMAX];
__device__ int   g_csr_src[EMAX];
__device__ int   g_part[(NMAX + SCAN_BLK - 1) / SCAN_BLK];
__device__ int   g_partscan[(NMAX + SCAN_BLK - 1) / SCAN_BLK];
__device__ float g_gsum[NGRAPH * HID];
__device__ float g_gcnt[NGRAPH];
__device__ float g_gatesX[NGRAPH * 4 * HID];
__device__ __half g_whh_h[4 * HID * HID];      // fp16 copy of w_hh (64 KB, L1-resident)

// ---------------- init ----------------
__global__ void k_init(int N) {
    int i = blockIdx.x * blockDim.x + threadIdx.x;
    if (i < N) g_deg[i] = 0;
    if (i < NGRAPH * HID) g_gsum[i] = 0.f;
    if (i < NGRAPH) g_gcnt[i] = 0.f;
}

// ---------------- degree histogram over col ----------------
__global__ void k_deg(const int* __restrict__ ei, int E) {
    int e = blockIdx.x * blockDim.x + threadIdx.x;
    if (e < E) atomicAdd(&g_deg[__ldg(&ei[(size_t)E + e])], 1);
}

// ---------------- scan pass 1: block sums + dinv ----------------
__global__ __launch_bounds__(SCAN_BLK) void k_scan1(int N) {
    int i = blockIdx.x * SCAN_BLK + threadIdx.x;
    int v = (i < N) ? g_deg[i] : 0;
    if (i < N) g_dinv[i] = rsqrtf((float)v + 1.0f);
    int s = v;
    for (int o = 16; o > 0; o >>= 1) s += __shfl_down_sync(0xffffffffu, s, o);
    __shared__ int ws[16];
    int wid = threadIdx.x >> 5, lane = threadIdx.x & 31;
    if (lane == 0) ws[wid] = s;
    __syncthreads();
    if (threadIdx.x < 16) {
        int t = ws[threadIdx.x];
        for (int o = 8; o > 0; o >>= 1) t += __shfl_down_sync(0xffffu, t, o);
        if (threadIdx.x == 0) g_part[blockIdx.x] = t;
    }
}

// ---------------- scan pass 2: parallel exclusive scan of <=256 block partials ----------------
__global__ __launch_bounds__(256) void k_scan2(int NB) {
    int tid = threadIdx.x;
    int v = (tid < NB) ? g_part[tid] : 0;
    int lane = tid & 31, wid = tid >> 5;
    int x = v;
    for (int o = 1; o < 32; o <<= 1) {
        int t = __shfl_up_sync(0xffffffffu, x, o);
        if (lane >= o) x += t;
    }
    __shared__ int ws[8];
    if (lane == 31) ws[wid] = x;
    __syncthreads();
    if (tid < 8) {
        int t = ws[tid];
        for (int o = 1; o < 8; o <<= 1) {
            int u = __shfl_up_sync(0xffu, t, o);
            if (tid >= o) t += u;
        }
        ws[tid] = t;
    }
    __syncthreads();
    int incl = x + (wid > 0 ? ws[wid - 1] : 0);
    if (tid < NB) g_partscan[tid] = incl - v;
}

// ---------------- scan pass 3: block exclusive scan -> g_start, g_cursor ----------------
__global__ __launch_bounds__(SCAN_BLK) void k_scan3(int N) {
    int i = blockIdx.x * SCAN_BLK + threadIdx.x;
    int v = (i < N) ? g_deg[i] : 0;
    int lane = threadIdx.x & 31, wid = threadIdx.x >> 5;
    int x = v;
    for (int o = 1; o < 32; o <<= 1) {
        int t = __shfl_up_sync(0xffffffffu, x, o);
        if (lane >= o) x += t;
    }
    __shared__ int ws[16];
    if (lane == 31) ws[wid] = x;
    __syncthreads();
    if (threadIdx.x < 16) {
        int t = ws[threadIdx.x];
        for (int o = 1; o < 16; o <<= 1) {
            int u = __shfl_up_sync(0xffffu, t, o);
            if (threadIdx.x >= o) t += u;
        }
        ws[threadIdx.x] = t;
    }
    __syncthreads();
    int base = g_partscan[blockIdx.x] + (wid > 0 ? ws[wid - 1] : 0);
    int excl = base + (x - v);
    if (i < N) { g_start[i] = excl; g_cursor[i] = excl; }
    if (i == N - 1) g_start[N] = excl + v;
}

// ---------------- CSR fill ----------------
__global__ void k_fill(const int* __restrict__ ei, int E) {
    int e = blockIdx.x * blockDim.x + threadIdx.x;
    if (e < E) {
        int row = __ldg(&ei[e]);
        int col = __ldg(&ei[(size_t)E + e]);
        int slot = atomicAdd(&g_cursor[col], 1);
        g_csr_src[slot] = row;
    }
}

// ---------------- convert w_hh to fp16 ----------------
__global__ void k_cvt(const float* __restrict__ w_hh) {
    int i = blockIdx.x * blockDim.x + threadIdx.x;
    if (i < 4 * HID * HID) g_whh_h[i] = __float2half(__ldg(&w_hh[i]));
}

// ---------------- GEMM: y[n] = fp16( dinv[n] * (x[n] @ W) ) ----------------
__global__ __launch_bounds__(512) void k_gemm(const float* __restrict__ x,
                                              const float* __restrict__ W, int M) {
    __shared__ float xsT[32][132];
    __shared__ float ws[32][128];
    int tid = threadIdx.x;
    int ty = tid >> 4, tx = tid & 15;   // ty 0..31 (4 rows), tx 0..15 (8 cols)
    int row0 = blockIdx.x * 128;

    float acc[4][8];
#pragma unroll
    for (int i = 0; i < 4; i++)
#pragma unroll
        for (int j = 0; j < 8; j++) acc[i][j] = 0.f;

    for (int kc = 0; kc < 128; kc += 32) {
#pragma unroll
        for (int it = 0; it < 2; it++) {
            int f4 = tid + it * 512;
            int r = f4 >> 3, kq = f4 & 7;
            int grow = row0 + r;
            float4 v = make_float4(0.f, 0.f, 0.f, 0.f);
            if (grow < M)
                v = __ldg((const float4*)(x + (size_t)grow * 128 + kc + kq * 4));
            xsT[kq * 4 + 0][r] = v.x;
            xsT[kq * 4 + 1][r] = v.y;
            xsT[kq * 4 + 2][r] = v.z;
            xsT[kq * 4 + 3][r] = v.w;
        }
#pragma unroll
        for (int it = 0; it < 2; it++) {
            int f4 = tid + it * 512;
            int wr = f4 >> 5, wc = (f4 & 31) * 4;
            float4 v = __ldg((const float4*)(W + (size_t)(kc + wr) * 128 + wc));
            *(float4*)&ws[wr][wc] = v;
        }
        __syncthreads();
#pragma unroll
        for (int k = 0; k < 32; k++) {
            float rx[4];
#pragma unroll
            for (int i = 0; i < 4; i++) rx[i] = xsT[k][ty * 4 + i];
            float4 wa = *(const float4*)&ws[k][tx * 8];
            float4 wb = *(const float4*)&ws[k][tx * 8 + 4];
            float rw[8] = {wa.x, wa.y, wa.z, wa.w, wb.x, wb.y, wb.z, wb.w};
#pragma unroll
            for (int i = 0; i < 4; i++)
#pragma unroll
                for (int j = 0; j < 8; j++) acc[i][j] = fmaf(rx[i], rw[j], acc[i][j]);
        }
        __syncthreads();
    }

#pragma unroll
    for (int i = 0; i < 4; i++) {
        int n = row0 + ty * 4 + i;
        if (n < M) {
            float dv = g_dinv[n];
            __half2 h0 = __floats2half2_rn(acc[i][0] * dv, acc[i][1] * dv);
            __half2 h1 = __floats2half2_rn(acc[i][2] * dv, acc[i][3] * dv);
            __half2 h2 = __floats2half2_rn(acc[i][4] * dv, acc[i][5] * dv);
            __half2 h3 = __floats2half2_rn(acc[i][6] * dv, acc[i][7] * dv);
            uint4 pack;
            pack.x = *(unsigned*)&h0; pack.y = *(unsigned*)&h1;
            pack.z = *(unsigned*)&h2; pack.w = *(unsigned*)&h3;
            *(uint4*)(g_yh + (size_t)n * HID + tx * 8) = pack;
        }
    }
}

// ---------------- fused gather-aggregate + relu + mean-pool (fp16 rows) ----------------
// One warp per node stride; lane holds dims [lane*4, lane*4+4) = one uint2 (4 halves).
__device__ __forceinline__ void pool_flush(int g, float4 run, float crun, int lane) {
    float* dst = g_gsum + g * HID + lane * 4;
    asm volatile("red.global.add.v4.f32 [%0], {%1,%2,%3,%4};"
                 :: "l"(dst), "f"(run.x), "f"(run.y), "f"(run.z), "f"(run.w) : "memory");
    if (lane == 0) atomicAdd(&g_gcnt[g], crun);
}

__device__ __forceinline__ void acc_row(float4& acc, int id, int lane) {
    uint2 r = __ldg((const uint2*)(g_yh + (size_t)id * HID) + lane);
    float2 lo = __half22float2(*(const __half2*)&r.x);
    float2 hi = __half22float2(*(const __half2*)&r.y);
    acc.x += lo.x; acc.y += lo.y; acc.z += hi.x; acc.w += hi.y;
}

__global__ __launch_bounds__(256) void k_agg(const int* __restrict__ batch,
                                             const float* __restrict__ b_gcn, int N) {
    int lane = threadIdx.x & 31, wid = threadIdx.x >> 5;
    int s0 = blockIdx.x * 128;
    int e0 = min(s0 + 128, N);
    int n0 = s0 + wid;
    if (n0 >= e0) return;

    float4 bb = __ldg((const float4*)(b_gcn + lane * 4));
    int curg = __ldg(&batch[n0]);
    float4 run = make_float4(0.f, 0.f, 0.f, 0.f);
    float crun = 0.f;

    for (int n = n0; n < e0; n += 8) {
        int gg = __ldg(&batch[n]);
        if (gg != curg) {
            pool_flush(curg, run, crun, lane);
            run = make_float4(0.f, 0.f, 0.f, 0.f);
            crun = 0.f;
            curg = gg;
        }
        int st = __ldg(&g_start[n]);
        int en = __ldg(&g_start[n + 1]);
        float4 acc = make_float4(0.f, 0.f, 0.f, 0.f);
        acc_row(acc, n, lane);   // self loop
        for (int base = st; base < en; base += 32) {
            int cnt = min(32, en - base);
            int id = (lane < cnt) ? __ldg(&g_csr_src[base + lane]) : 0;
            int j = 0;
            for (; j + 4 <= cnt; j += 4) {
                int a0 = __shfl_sync(0xffffffffu, id, j);
                int a1 = __shfl_sync(0xffffffffu, id, j + 1);
                int a2 = __shfl_sync(0xffffffffu, id, j + 2);
                int a3 = __shfl_sync(0xffffffffu, id, j + 3);
                acc_row(acc, a0, lane);
                acc_row(acc, a1, lane);
                acc_row(acc, a2, lane);
                acc_row(acc, a3, lane);
            }
            for (; j < cnt; j++) {
                int a0 = __shfl_sync(0xffffffffu, id, j);
                acc_row(acc, a0, lane);
            }
        }
        float dv = __ldg(&g_dinv[n]);
        run.x += fmaxf(fmaf(acc.x, dv, bb.x), 0.f);
        run.y += fmaxf(fmaf(acc.y, dv, bb.y), 0.f);
        run.z += fmaxf(fmaf(acc.z, dv, bb.z), 0.f);
        run.w += fmaxf(fmaf(acc.w, dv, bb.w), 0.f);
        crun += 1.f;
    }
    pool_flush(curg, run, crun, lane);
}

// ---------------- input-side LSTM gates ----------------
__global__ __launch_bounds__(512) void k_gatesx(const float* __restrict__ w_ih,
                                                const float* __restrict__ b_ih,
                                                const float* __restrict__ b_hh) {
    __shared__ float p[HID];
    int t = blockIdx.x;
    if (threadIdx.x < HID) {
        float c = fmaxf(g_gcnt[t], 1.f);
        p[threadIdx.x] = g_gsum[t * HID + threadIdx.x] / c;
    }
    __syncthreads();
    int gg = threadIdx.x;
    const float4* wr = (const float4*)(w_ih + (size_t)gg * HID);
    float acc = __ldg(&b_ih[gg]) + __ldg(&b_hh[gg]);
#pragma unroll
    for (int j = 0; j < 32; j++) {
        float4 w = __ldg(wr + j);
        acc += w.x * p[j * 4] + w.y * p[j * 4 + 1] + w.z * p[j * 4 + 2] + w.w * p[j * 4 + 3];
    }
    g_gatesX[t * 512 + gg] = acc;
}

// ---------------- recurrent LSTM (fp16 weights, L1-resident) + fused FC ----------------
__global__ __launch_bounds__(512) void k_lstm(const float* __restrict__ W_fc,
                                              const float* __restrict__ b_fc,
                                              float* __restrict__ out) {
    __shared__ float sh[HID];
    __shared__ float sg[4 * HID];
    int tid = threadIdx.x;
    float c = 0.f;
    if (tid < HID) sh[tid] = 0.f;
    __syncthreads();
    const uint4* wr = (const uint4*)(g_whh_h + (size_t)tid * HID);
    for (int t = 0; t < NGRAPH; t++) {
        float acc = g_gatesX[t * 512 + tid];
#pragma unroll
        for (int j = 0; j < 16; j++) {
            uint4 w = __ldg(&wr[j]);
            float2 a0 = __half22float2(*(const __half2*)&w.x);
            float2 a1 = __half22float2(*(const __half2*)&w.y);
            float2 a2 = __half22float2(*(const __half2*)&w.z);
            float2 a3 = __half22float2(*(const __half2*)&w.w);
            const float* h = &sh[j * 8];
            acc = fmaf(a0.x, h[0], acc); acc = fmaf(a0.y, h[1], acc);
            acc = fmaf(a1.x, h[2], acc); acc = fmaf(a1.y, h[3], acc);
            acc = fmaf(a2.x, h[4], acc); acc = fmaf(a2.y, h[5], acc);
            acc = fmaf(a3.x, h[6], acc); acc = fmaf(a3.y, h[7], acc);
        }
        sg[tid] = acc;
        __syncthreads();
        if (tid < HID) {
            float iv = 1.f / (1.f + __expf(-sg[tid]));
            float fv = 1.f / (1.f + __expf(-sg[HID + tid]));
            float gv = tanhf(sg[2 * HID + tid]);
            float ov = 1.f / (1.f + __expf(-sg[3 * HID + tid]));
            c = fv * c + iv * gv;
            sh[tid] = ov * tanhf(c);
        }
        __syncthreads();
        if (tid < 320) {
            int k = tid >> 5, lane = tid & 31;
            const float4* wf = (const float4*)(W_fc + (size_t)k * HID);
            float4 w = __ldg(&wf[lane]);
            float4 h4 = *(const float4*)&sh[lane * 4];
            float p = w.x * h4.x + w.y * h4.y + w.z * h4.z + w.w * h4.w;
            for (int o = 16; o > 0; o >>= 1) p += __shfl_down_sync(0xffffffffu, p, o);
            if (lane == 0) out[t * 10 + k] = p + __ldg(&b_fc[k]);
        }
    }
}

// ---------------- launch: fork GEMM onto a side stream, join before k_agg ----------------
extern "C" void kernel_launch(void* const* d_in, const int* in_sizes, int n_in,
                              void* d_out, int out_size) {
    const float* x      = (const float*)d_in[0];
    const int*   ei     = (const int*)d_in[1];
    const int*   batch  = (const int*)d_in[2];
    const float* W_gcn  = (const float*)d_in[3];
    const float* b_gcn  = (const float*)d_in[4];
    const float* w_ih   = (const float*)d_in[5];
    const float* w_hh   = (const float*)d_in[6];
    const float* b_ih   = (const float*)d_in[7];
    const float* b_hh   = (const float*)d_in[8];
    const float* W_fc   = (const float*)d_in[9];
    const float* b_fc   = (const float*)d_in[10];
    float* out = (float*)d_out;

    int N = in_sizes[2];       // 100000 nodes
    int E = in_sizes[1] / 2;   // 1600000 edges
    int NB = (N + SCAN_BLK - 1) / SCAN_BLK;

    static cudaStream_t s2 = nullptr;
    static cudaEvent_t evA = nullptr, evB = nullptr;
    if (s2 == nullptr) {
        cudaStreamCreate(&s2);
        cudaEventCreateWithFlags(&evA, cudaEventDisableTiming);
        cudaEventCreateWithFlags(&evB, cudaEventDisableTiming);
    }

    k_init<<<(N + 255) / 256, 256>>>(N);
    k_deg<<<(E + 255) / 256, 256>>>(ei, E);
    k_scan1<<<NB, SCAN_BLK>>>(N);               // produces g_dinv + block partials

    // fork: GEMM (needs only dinv) runs alongside scan2/scan3/fill
    cudaEventRecord(evA, 0);
    cudaStreamWaitEvent(s2, evA, 0);
    k_gemm<<<(N + 127) / 128, 512, 0, s2>>>(x, W_gcn, N);
    k_cvt<<<(4 * HID * HID + 255) / 256, 256, 0, s2>>>(w_hh);
    cudaEventRecord(evB, s2);

    k_scan2<<<1, 256>>>(NB);
    k_scan3<<<NB, SCAN_BLK>>>(N);
    k_fill<<<(E + 255) / 256, 256>>>(ei, E);

    // join: agg needs both CSR (main) and y (s2)
    cudaStreamWaitEvent(0, evB, 0);
    k_agg<<<(N + 127) / 128, 256>>>(batch, b_gcn, N);
    k_gatesx<<<NGRAPH, 512>>>(w_ih, b_ih, b_hh);
    k_lstm<<<1, 512>>>(W_fc, b_fc, out);
}

// round 6
// speedup vs baseline: 2.3734x; 1.2104x over previous
#include <cuda_runtime.h>
#include <cuda_fp16.h>
#include <math.h>

#define NMAX 100000
#define EMAX 1600000
#define HID 128
#define NGRAPH 64
#define SCAN_BLK 512

// ---------------- device scratch ----------------
__device__ __half g_xh[(size_t)NMAX * HID];    // fp16 copy of x
__device__ __half g_wt[HID * HID];             // fp16 W_gcn transposed: wt[n][k] = W[k][n]
__device__ __half g_yh[(size_t)NMAX * HID];    // fp16: dinv[n] * (x @ W_gcn)[n]
__device__ float g_dinv[NMAX];
__device__ int   g_deg[NMAX];
__device__ int   g_start[NMAX + 1];
__device__ int   g_cursor[NMAX];
__device__ int   g_csr_src[EMAX];
__device__ int   g_part[(NMAX + SCAN_BLK - 1) / SCAN_BLK];
__device__ int   g_partscan[(NMAX + SCAN_BLK - 1) / SCAN_BLK];
__device__ float g_gsum[NGRAPH * HID];
__device__ float g_gcnt[NGRAPH];
__device__ float g_gatesX[NGRAPH * 4 * HID];
__device__ __half g_whh_h[4 * HID * HID];      // fp16 copy of w_hh (64 KB, L1-resident)

// ---------------- fp16 conversions ----------------
__global__ void k_cvtx(const float* __restrict__ x, int total8) {  // total8 = N*HID/8
    int i = blockIdx.x * blockDim.x + threadIdx.x;
    if (i < total8) {
        float4 v0 = __ldg((const float4*)x + (size_t)i * 2);
        float4 v1 = __ldg((const float4*)x + (size_t)i * 2 + 1);
        __half2 h0 = __floats2half2_rn(v0.x, v0.y);
        __half2 h1 = __floats2half2_rn(v0.z, v0.w);
        __half2 h2 = __floats2half2_rn(v1.x, v1.y);
        __half2 h3 = __floats2half2_rn(v1.z, v1.w);
        uint4 p;
        p.x = *(unsigned*)&h0; p.y = *(unsigned*)&h1;
        p.z = *(unsigned*)&h2; p.w = *(unsigned*)&h3;
        *(uint4*)(g_xh + (size_t)i * 8) = p;
    }
}

__global__ void k_cvtw(const float* __restrict__ W) {
    int i = blockIdx.x * blockDim.x + threadIdx.x;   // 16384
    if (i < HID * HID) {
        int n = i >> 7, k = i & 127;
        g_wt[n * HID + k] = __float2half(__ldg(&W[k * HID + n]));
    }
}

__global__ void k_cvtwhh(const float* __restrict__ w_hh) {
    int i = blockIdx.x * blockDim.x + threadIdx.x;
    if (i < 4 * HID * HID) g_whh_h[i] = __float2half(__ldg(&w_hh[i]));
}

// ---------------- init ----------------
__global__ void k_init(int N) {
    int i = blockIdx.x * blockDim.x + threadIdx.x;
    if (i < N) g_deg[i] = 0;
    if (i < NGRAPH * HID) g_gsum[i] = 0.f;
    if (i < NGRAPH) g_gcnt[i] = 0.f;
}

// ---------------- degree histogram over col ----------------
__global__ void k_deg(const int* __restrict__ ei, int E) {
    int e = blockIdx.x * blockDim.x + threadIdx.x;
    if (e < E) atomicAdd(&g_deg[__ldg(&ei[(size_t)E + e])], 1);
}

// ---------------- scan pass 1: block sums + dinv ----------------
__global__ __launch_bounds__(SCAN_BLK) void k_scan1(int N) {
    int i = blockIdx.x * SCAN_BLK + threadIdx.x;
    int v = (i < N) ? g_deg[i] : 0;
    if (i < N) g_dinv[i] = rsqrtf((float)v + 1.0f);
    int s = v;
    for (int o = 16; o > 0; o >>= 1) s += __shfl_down_sync(0xffffffffu, s, o);
    __shared__ int ws[16];
    int wid = threadIdx.x >> 5, lane = threadIdx.x & 31;
    if (lane == 0) ws[wid] = s;
    __syncthreads();
    if (threadIdx.x < 16) {
        int t = ws[threadIdx.x];
        for (int o = 8; o > 0; o >>= 1) t += __shfl_down_sync(0xffffu, t, o);
        if (threadIdx.x == 0) g_part[blockIdx.x] = t;
    }
}

// ---------------- scan pass 2 ----------------
__global__ __launch_bounds__(256) void k_scan2(int NB) {
    int tid = threadIdx.x;
    int v = (tid < NB) ? g_part[tid] : 0;
    int lane = tid & 31, wid = tid >> 5;
    int x = v;
    for (int o = 1; o < 32; o <<= 1) {
        int t = __shfl_up_sync(0xffffffffu, x, o);
        if (lane >= o) x += t;
    }
    __shared__ int ws[8];
    if (lane == 31) ws[wid] = x;
    __syncthreads();
    if (tid < 8) {
        int t = ws[tid];
        for (int o = 1; o < 8; o <<= 1) {
            int u = __shfl_up_sync(0xffu, t, o);
            if (tid >= o) t += u;
        }
        ws[tid] = t;
    }
    __syncthreads();
    int incl = x + (wid > 0 ? ws[wid - 1] : 0);
    if (tid < NB) g_partscan[tid] = incl - v;
}

// ---------------- scan pass 3 ----------------
__global__ __launch_bounds__(SCAN_BLK) void k_scan3(int N) {
    int i = blockIdx.x * SCAN_BLK + threadIdx.x;
    int v = (i < N) ? g_deg[i] : 0;
    int lane = threadIdx.x & 31, wid = threadIdx.x >> 5;
    int x = v;
    for (int o = 1; o < 32; o <<= 1) {
        int t = __shfl_up_sync(0xffffffffu, x, o);
        if (lane >= o) x += t;
    }
    __shared__ int ws[16];
    if (lane == 31) ws[wid] = x;
    __syncthreads();
    if (threadIdx.x < 16) {
        int t = ws[threadIdx.x];
        for (int o = 1; o < 16; o <<= 1) {
            int u = __shfl_up_sync(0xffffu, t, o);
            if (threadIdx.x >= o) t += u;
        }
        ws[threadIdx.x] = t;
    }
    __syncthreads();
    int base = g_partscan[blockIdx.x] + (wid > 0 ? ws[wid - 1] : 0);
    int excl = base + (x - v);
    if (i < N) { g_start[i] = excl; g_cursor[i] = excl; }
    if (i == N - 1) g_start[N] = excl + v;
}

// ---------------- CSR fill ----------------
__global__ void k_fill(const int* __restrict__ ei, int E) {
    int e = blockIdx.x * blockDim.x + threadIdx.x;
    if (e < E) {
        int row = __ldg(&ei[e]);
        int col = __ldg(&ei[(size_t)E + e]);
        int slot = atomicAdd(&g_cursor[col], 1);
        g_csr_src[slot] = row;
    }
}

// ---------------- tensor-core GEMM: y[n] = fp16( dinv[n] * (x[n] @ W) ) ----------------
// 256 threads = 8 warps; block tile 128m x 128n; warp tile 32m x 64n.
// K=128 staged in two 64-wide smem chunks. Manual m16n8k16 fragments.
__global__ __launch_bounds__(256) void k_gemm_tc(int M) {
    __shared__ __half xs[128][72];   // [m][k], stride 72 halves (bank-safe)
    __shared__ __half ws[128][72];   // [n][k]
    int tid = threadIdx.x;
    int warp = tid >> 5, lane = tid & 31;
    int wm = (warp & 3) * 32;
    int wn = (warp >> 2) * 64;
    int g = lane >> 2, tig = lane & 3;
    int m0 = blockIdx.x * 128;

    float acc[2][8][4];
#pragma unroll
    for (int mt = 0; mt < 2; mt++)
#pragma unroll
        for (int nt = 0; nt < 8; nt++)
#pragma unroll
            for (int q = 0; q < 4; q++) acc[mt][nt][q] = 0.f;

    for (int kc = 0; kc < 2; kc++) {
#pragma unroll
        for (int i = 0; i < 4; i++) {
            int idx = i * 256 + tid;      // 0..1023
            int r = idx >> 3, q = idx & 7;
            int grow = m0 + r;
            uint4 v = make_uint4(0u, 0u, 0u, 0u);
            if (grow < M)
                v = *(const uint4*)(g_xh + (size_t)grow * HID + kc * 64 + q * 8);
            *(uint4*)(&xs[r][q * 8]) = v;
            uint4 w = *(const uint4*)(g_wt + r * HID + kc * 64 + q * 8);
            *(uint4*)(&ws[r][q * 8]) = w;
        }
        __syncthreads();
#pragma unroll
        for (int ks = 0; ks < 4; ks++) {
            int k0 = ks * 16;
            unsigned a[2][4];
#pragma unroll
            for (int mt = 0; mt < 2; mt++) {
                int row = wm + mt * 16 + g;
                a[mt][0] = *(const unsigned*)(&xs[row][k0 + tig * 2]);
                a[mt][1] = *(const unsigned*)(&xs[row + 8][k0 + tig * 2]);
                a[mt][2] = *(const unsigned*)(&xs[row][k0 + tig * 2 + 8]);
                a[mt][3] = *(const unsigned*)(&xs[row + 8][k0 + tig * 2 + 8]);
            }
#pragma unroll
            for (int nt = 0; nt < 8; nt++) {
                int n = wn + nt * 8 + g;
                unsigned b0 = *(const unsigned*)(&ws[n][k0 + tig * 2]);
                unsigned b1 = *(const unsigned*)(&ws[n][k0 + tig * 2 + 8]);
#pragma unroll
                for (int mt = 0; mt < 2; mt++) {
                    float* c = acc[mt][nt];
                    asm volatile(
                        "mma.sync.aligned.m16n8k16.row.col.f32.f16.f16.f32 "
                        "{%0,%1,%2,%3}, {%4,%5,%6,%7}, {%8,%9}, {%0,%1,%2,%3};"
                        : "+f"(c[0]), "+f"(c[1]), "+f"(c[2]), "+f"(c[3])
                        : "r"(a[mt][0]), "r"(a[mt][1]), "r"(a[mt][2]), "r"(a[mt][3]),
                          "r"(b0), "r"(b1));
                }
            }
        }
        __syncthreads();
    }

#pragma unroll
    for (int mt = 0; mt < 2; mt++) {
        int row = m0 + wm + mt * 16 + g;
        float dv0 = (row < M) ? g_dinv[row] : 0.f;
        float dv8 = (row + 8 < M) ? g_dinv[row + 8] : 0.f;
#pragma unroll
        for (int nt = 0; nt < 8; nt++) {
            int col = wn + nt * 8 + tig * 2;
            float* c = acc[mt][nt];
            if (row < M) {
                __half2 h = __floats2half2_rn(c[0] * dv0, c[1] * dv0);
                *(__half2*)(g_yh + (size_t)row * HID + col) = h;
            }
            if (row + 8 < M) {
                __half2 h = __floats2half2_rn(c[2] * dv8, c[3] * dv8);
                *(__half2*)(g_yh + (size_t)(row + 8) * HID + col) = h;
            }
        }
    }
}

// ---------------- fused gather-aggregate + relu + mean-pool (fp16 rows) ----------------
__device__ __forceinline__ void pool_flush(int g, float4 run, float crun, int lane) {
    float* dst = g_gsum + g * HID + lane * 4;
    asm volatile("red.global.add.v4.f32 [%0], {%1,%2,%3,%4};"
                 :: "l"(dst), "f"(run.x), "f"(run.y), "f"(run.z), "f"(run.w) : "memory");
    if (lane == 0) atomicAdd(&g_gcnt[g], crun);
}

__device__ __forceinline__ void acc_row(float4& acc, int id, int lane) {
    uint2 r = __ldg((const uint2*)(g_yh + (size_t)id * HID) + lane);
    float2 lo = __half22float2(*(const __half2*)&r.x);
    float2 hi = __half22float2(*(const __half2*)&r.y);
    acc.x += lo.x; acc.y += lo.y; acc.z += hi.x; acc.w += hi.y;
}

__global__ __launch_bounds__(256) void k_agg(const int* __restrict__ batch,
                                             const float* __restrict__ b_gcn, int N) {
    int lane = threadIdx.x & 31, wid = threadIdx.x >> 5;
    int s0 = blockIdx.x * 128;
    int e0 = min(s0 + 128, N);
    int n0 = s0 + wid;
    if (n0 >= e0) return;

    float4 bb = __ldg((const float4*)(b_gcn + lane * 4));
    int curg = __ldg(&batch[n0]);
    float4 run = make_float4(0.f, 0.f, 0.f, 0.f);
    float crun = 0.f;

    for (int n = n0; n < e0; n += 8) {
        int gg = __ldg(&batch[n]);
        if (gg != curg) {
            pool_flush(curg, run, crun, lane);
            run = make_float4(0.f, 0.f, 0.f, 0.f);
            crun = 0.f;
            curg = gg;
        }
        int st = __ldg(&g_start[n]);
        int en = __ldg(&g_start[n + 1]);
        float4 acc = make_float4(0.f, 0.f, 0.f, 0.f);
        acc_row(acc, n, lane);   // self loop
        for (int base = st; base < en; base += 32) {
            int cnt = min(32, en - base);
            int id = (lane < cnt) ? __ldg(&g_csr_src[base + lane]) : 0;
            int j = 0;
            for (; j + 4 <= cnt; j += 4) {
                int a0 = __shfl_sync(0xffffffffu, id, j);
                int a1 = __shfl_sync(0xffffffffu, id, j + 1);
                int a2 = __shfl_sync(0xffffffffu, id, j + 2);
                int a3 = __shfl_sync(0xffffffffu, id, j + 3);
                acc_row(acc, a0, lane);
                acc_row(acc, a1, lane);
                acc_row(acc, a2, lane);
                acc_row(acc, a3, lane);
            }
            for (; j < cnt; j++) {
                int a0 = __shfl_sync(0xffffffffu, id, j);
                acc_row(acc, a0, lane);
            }
        }
        float dv = __ldg(&g_dinv[n]);
        run.x += fmaxf(fmaf(acc.x, dv, bb.x), 0.f);
        run.y += fmaxf(fmaf(acc.y, dv, bb.y), 0.f);
        run.z += fmaxf(fmaf(acc.z, dv, bb.z), 0.f);
        run.w += fmaxf(fmaf(acc.w, dv, bb.w), 0.f);
        crun += 1.f;
    }
    pool_flush(curg, run, crun, lane);
}

// ---------------- input-side LSTM gates ----------------
__global__ __launch_bounds__(512) void k_gatesx(const float* __restrict__ w_ih,
                                                const float* __restrict__ b_ih,
                                                const float* __restrict__ b_hh) {
    __shared__ float p[HID];
    int t = blockIdx.x;
    if (threadIdx.x < HID) {
        float c = fmaxf(g_gcnt[t], 1.f);
        p[threadIdx.x] = g_gsum[t * HID + threadIdx.x] / c;
    }
    __syncthreads();
    int gg = threadIdx.x;
    const float4* wr = (const float4*)(w_ih + (size_t)gg * HID);
    float acc = __ldg(&b_ih[gg]) + __ldg(&b_hh[gg]);
#pragma unroll
    for (int j = 0; j < 32; j++) {
        float4 w = __ldg(wr + j);
        acc += w.x * p[j * 4] + w.y * p[j * 4 + 1] + w.z * p[j * 4 + 2] + w.w * p[j * 4 + 3];
    }
    g_gatesX[t * 512 + gg] = acc;
}

// ---------------- recurrent LSTM (fp16 weights, L1-resident) + fused FC ----------------
__global__ __launch_bounds__(512) void k_lstm(const float* __restrict__ W_fc,
                                              const float* __restrict__ b_fc,
                                              float* __restrict__ out) {
    __shared__ float sh[HID];
    __shared__ float sg[4 * HID];
    int tid = threadIdx.x;
    float c = 0.f;
    if (tid < HID) sh[tid] = 0.f;
    __syncthreads();
    const uint4* wr = (const uint4*)(g_whh_h + (size_t)tid * HID);
    for (int t = 0; t < NGRAPH; t++) {
        float acc = g_gatesX[t * 512 + tid];
#pragma unroll
        for (int j = 0; j < 16; j++) {
            uint4 w = __ldg(&wr[j]);
            float2 a0 = __half22float2(*(const __half2*)&w.x);
            float2 a1 = __half22float2(*(const __half2*)&w.y);
            float2 a2 = __half22float2(*(const __half2*)&w.z);
            float2 a3 = __half22float2(*(const __half2*)&w.w);
            const float* h = &sh[j * 8];
            acc = fmaf(a0.x, h[0], acc); acc = fmaf(a0.y, h[1], acc);
            acc = fmaf(a1.x, h[2], acc); acc = fmaf(a1.y, h[3], acc);
            acc = fmaf(a2.x, h[4], acc); acc = fmaf(a2.y, h[5], acc);
            acc = fmaf(a3.x, h[6], acc); acc = fmaf(a3.y, h[7], acc);
        }
        sg[tid] = acc;
        __syncthreads();
        if (tid < HID) {
            float iv = 1.f / (1.f + __expf(-sg[tid]));
            float fv = 1.f / (1.f + __expf(-sg[HID + tid]));
            float gv = tanhf(sg[2 * HID + tid]);
            float ov = 1.f / (1.f + __expf(-sg[3 * HID + tid]));
            c = fv * c + iv * gv;
            sh[tid] = ov * tanhf(c);
        }
        __syncthreads();
        if (tid < 320) {
            int k = tid >> 5, lane = tid & 31;
            const float4* wf = (const float4*)(W_fc + (size_t)k * HID);
            float4 w = __ldg(&wf[lane]);
            float4 h4 = *(const float4*)&sh[lane * 4];
            float p = w.x * h4.x + w.y * h4.y + w.z * h4.z + w.w * h4.w;
            for (int o = 16; o > 0; o >>= 1) p += __shfl_down_sync(0xffffffffu, p, o);
            if (lane == 0) out[t * 10 + k] = p + __ldg(&b_fc[k]);
        }
    }
}

// ---------------- launch ----------------
extern "C" void kernel_launch(void* const* d_in, const int* in_sizes, int n_in,
                              void* d_out, int out_size) {
    const float* x      = (const float*)d_in[0];
    const int*   ei     = (const int*)d_in[1];
    const int*   batch  = (const int*)d_in[2];
    const float* W_gcn  = (const float*)d_in[3];
    const float* b_gcn  = (const float*)d_in[4];
    const float* w_ih   = (const float*)d_in[5];
    const float* w_hh   = (const float*)d_in[6];
    const float* b_ih   = (const float*)d_in[7];
    const float* b_hh   = (const float*)d_in[8];
    const float* W_fc   = (const float*)d_in[9];
    const float* b_fc   = (const float*)d_in[10];
    float* out = (float*)d_out;

    int N = in_sizes[2];       // 100000 nodes
    int E = in_sizes[1] / 2;   // 1600000 edges
    int NB = (N + SCAN_BLK - 1) / SCAN_BLK;

    static cudaStream_t s2 = nullptr;
    static cudaEvent_t ev0 = nullptr, evA = nullptr, evB = nullptr;
    if (s2 == nullptr) {
        cudaStreamCreate(&s2);
        cudaEventCreateWithFlags(&ev0, cudaEventDisableTiming);
        cudaEventCreateWithFlags(&evA, cudaEventDisableTiming);
        cudaEventCreateWithFlags(&evB, cudaEventDisableTiming);
    }

    // fork s2 at start: fp16 conversions have no dependencies
    cudaEventRecord(ev0, 0);
    cudaStreamWaitEvent(s2, ev0, 0);
    k_cvtx<<<(N * HID / 8 + 255) / 256, 256, 0, s2>>>(x, N * HID / 8);
    k_cvtw<<<(HID * HID + 255) / 256, 256, 0, s2>>>(W_gcn);

    k_init<<<(N + 255) / 256, 256>>>(N);
    k_deg<<<(E + 255) / 256, 256>>>(ei, E);
    k_scan1<<<NB, SCAN_BLK>>>(N);               // produces g_dinv + block partials

    // gemm on s2 after dinv ready (also after cvtx/cvtw in s2 order)
    cudaEventRecord(evA, 0);
    cudaStreamWaitEvent(s2, evA, 0);
    k_gemm_tc<<<(N + 127) / 128, 256, 0, s2>>>(N);
    k_cvtwhh<<<(4 * HID * HID + 255) / 256, 256, 0, s2>>>(w_hh);
    cudaEventRecord(evB, s2);

    k_scan2<<<1, 256>>>(NB);
    k_scan3<<<NB, SCAN_BLK>>>(N);
    k_fill<<<(E + 255) / 256, 256>>>(ei, E);

    // join: agg needs CSR (main) + y (s2)
    cudaStreamWaitEvent(0, evB, 0);
    k_agg<<<(N + 127) / 128, 256>>>(batch, b_gcn, N);
    k_gatesx<<<NGRAPH, 512>>>(w_ih, b_ih, b_hh);
    k_lstm<<<1, 512>>>(W_fc, b_fc, out);
}